// round 1
// baseline (speedup 1.0000x reference)
#include <cuda_runtime.h>
#include <math.h>

// ---------------- problem constants ----------------
#define BATCH   4
#define SEQ     2048
#define HID     1024
#define DS      256          // per-scale dim
#define NH      2            // heads per scale
#define HD      128          // head dim
#define MROWS   (BATCH*SEQ)  // 8192

// ---------------- scratch (device globals; no allocation allowed) ----------------
__device__ float g_Q [MROWS*HID];
__device__ float g_K [MROWS*HID];
__device__ float g_V [MROWS*HID];
__device__ float g_QH[4L*MROWS*DS];
__device__ float g_KH[4L*MROWS*DS];
__device__ float g_VH[4L*MROWS*DS];
__device__ float g_KP[4L*BATCH*(SEQ/2)*DS];
__device__ float g_VP[4L*BATCH*(SEQ/2)*DS];
__device__ float g_S [(long long)BATCH*NH*SEQ*SEQ];   // 33.5M floats (reused per scale)
__device__ float g_OH[MROWS*DS];                      // reused per scale
__device__ float g_ATT[MROWS*HID];

// ---------------- generic tiled GEMM ----------------
// C = alpha * A @ op(B) + bias        (op(B)=B^T when TB, else B)
// A: M x K row-major (lda), B: TB ? N x K : K x N row-major (ldb), C: M x N (ldc)
// batched over blockIdx.z = b*nh + h with independent strides for batch and head.
#define BM 64
#define BN 64
#define BK 16
#define PAD 4

template<bool TB>
__global__ void __launch_bounds__(256)
gemm_kernel(const float* __restrict__ A, const float* __restrict__ Bm,
            const float* __restrict__ bias, float* __restrict__ C,
            int M, int N, int K, int lda, int ldb, int ldc,
            long long sAb, long long sAh, long long sBb, long long sBh,
            long long sCb, long long sCh, int nh, float alpha)
{
    int z  = blockIdx.z;
    int bb = z / nh, hh = z - bb * nh;
    A  += (long long)bb * sAb + (long long)hh * sAh;
    Bm += (long long)bb * sBb + (long long)hh * sBh;
    C  += (long long)bb * sCb + (long long)hh * sCh;

    __shared__ float As[BK][BM + PAD];
    __shared__ float Bs[BK][BN + PAD];

    const int tid  = threadIdx.x;
    const int row0 = blockIdx.y * BM;
    const int col0 = blockIdx.x * BN;
    const int tx   = tid & 15;
    const int ty   = tid >> 4;

    float acc[4][4];
#pragma unroll
    for (int i = 0; i < 4; i++)
#pragma unroll
        for (int j = 0; j < 4; j++) acc[i][j] = 0.f;

    const int ar = tid >> 2;          // 0..63
    const int ak = (tid & 3) << 2;    // 0,4,8,12

    for (int k0 = 0; k0 < K; k0 += BK) {
        // load A tile (BM x BK), K assumed multiple of 16 (true for all call sites)
        {
            float4 av = make_float4(0.f, 0.f, 0.f, 0.f);
            if (row0 + ar < M)
                av = *reinterpret_cast<const float4*>(A + (long long)(row0 + ar) * lda + (k0 + ak));
            As[ak + 0][ar] = av.x; As[ak + 1][ar] = av.y;
            As[ak + 2][ar] = av.z; As[ak + 3][ar] = av.w;
        }
        if (TB) {
            float4 bv = make_float4(0.f, 0.f, 0.f, 0.f);
            if (col0 + ar < N)
                bv = *reinterpret_cast<const float4*>(Bm + (long long)(col0 + ar) * ldb + (k0 + ak));
            Bs[ak + 0][ar] = bv.x; Bs[ak + 1][ar] = bv.y;
            Bs[ak + 2][ar] = bv.z; Bs[ak + 3][ar] = bv.w;
        } else {
            int bk = tid >> 4;            // 0..15
            int bn = (tid & 15) << 2;     // 0..60
            float4 bv = make_float4(0.f, 0.f, 0.f, 0.f);
            if (col0 + bn < N)
                bv = *reinterpret_cast<const float4*>(Bm + (long long)(k0 + bk) * ldb + (col0 + bn));
            *reinterpret_cast<float4*>(&Bs[bk][bn]) = bv;
        }
        __syncthreads();

#pragma unroll
        for (int kk = 0; kk < BK; kk++) {
            float4 a4 = *reinterpret_cast<const float4*>(&As[kk][ty << 2]);
            float4 b4 = *reinterpret_cast<const float4*>(&Bs[kk][tx << 2]);
            float a[4] = {a4.x, a4.y, a4.z, a4.w};
            float b[4] = {b4.x, b4.y, b4.z, b4.w};
#pragma unroll
            for (int i = 0; i < 4; i++)
#pragma unroll
                for (int j = 0; j < 4; j++)
                    acc[i][j] = fmaf(a[i], b[j], acc[i][j]);
        }
        __syncthreads();
    }

#pragma unroll
    for (int i = 0; i < 4; i++) {
        int r = row0 + (ty << 2) + i;
        if (r >= M) continue;
#pragma unroll
        for (int j = 0; j < 4; j++) {
            int c = col0 + (tx << 2) + j;
            if (c >= N) continue;
            float v = acc[i][j] * alpha;
            if (bias) v += bias[c];
            C[(long long)r * ldc + c] = v;
        }
    }
}

// ---------------- avg-pool of a DS-wide column slice along seq ----------------
// Y[r][c] = mean_{j<s} X[r*s + j][colOff + c],  r in [0, B*Lp),  X row stride = HID
__global__ void pool_kernel(const float* __restrict__ X, float* __restrict__ Y,
                            int rows, int s, int colOff)
{
    int idx = blockIdx.x * blockDim.x + threadIdx.x;
    int total = rows * DS;
    if (idx >= total) return;
    int r = idx / DS, c = idx - r * DS;
    const float* src = X + (long long)r * s * HID + colOff + c;
    float acc = 0.f;
    for (int j = 0; j < s; j++) acc += src[(long long)j * HID];
    Y[idx] = acc * (1.f / s);
}

// ---------------- in-place row softmax ----------------
__global__ void softmax_kernel(float* __restrict__ S, int Lk)
{
    long long row = (long long)blockIdx.y * gridDim.x + blockIdx.x;
    float* p = S + row * Lk;
    __shared__ float red[256];
    int tid = threadIdx.x;

    float m = -1e30f;
    for (int i = tid; i < Lk; i += 256) m = fmaxf(m, p[i]);
    red[tid] = m; __syncthreads();
    for (int s = 128; s > 0; s >>= 1) {
        if (tid < s) red[tid] = fmaxf(red[tid], red[tid + s]);
        __syncthreads();
    }
    m = red[0]; __syncthreads();

    float sum = 0.f;
    for (int i = tid; i < Lk; i += 256) {
        float e = __expf(p[i] - m);
        p[i] = e; sum += e;
    }
    red[tid] = sum; __syncthreads();
    for (int s = 128; s > 0; s >>= 1) {
        if (tid < s) red[tid] += red[tid + s];
        __syncthreads();
    }
    float inv = 1.f / red[0];
    for (int i = tid; i < Lk; i += 256) p[i] *= inv;
}

// ---------------- mean of 2 heads of scale-0 probs -> weights0 ----------------
__global__ void meanw_kernel(const float* __restrict__ S, float* __restrict__ W)
{
    long long idx = (long long)blockIdx.x * blockDim.x + threadIdx.x;
    const long long per = (long long)SEQ * SEQ;
    const long long total = (long long)BATCH * per;
    if (idx >= total) return;
    long long b = idx / per, rest = idx - b * per;
    W[idx] = 0.5f * (S[(b * 2 + 0) * per + rest] + S[(b * 2 + 1) * per + rest]);
}

// ---------------- host orchestration ----------------
extern "C" void kernel_launch(void* const* d_in, const int* in_sizes, int n_in,
                              void* d_out, int out_size)
{
    const float* query = (const float*)d_in[0];
    const float* key_  = (const float*)d_in[1];
    const float* value = (const float*)d_in[2];
    const float* wq    = (const float*)d_in[3];
    const float* bq    = (const float*)d_in[4];
    const float* wk    = (const float*)d_in[5];
    const float* bk    = (const float*)d_in[6];
    const float* wv    = (const float*)d_in[7];
    const float* bv    = (const float*)d_in[8];
    const float* in_w  = (const float*)d_in[9];   // (4, 768, 256)
    const float* in_b  = (const float*)d_in[10];  // (4, 768)
    const float* out_w = (const float*)d_in[11];  // (4, 256, 256)
    const float* out_b = (const float*)d_in[12];  // (4, 256)
    const float* fus_w = (const float*)d_in[13];
    const float* fus_b = (const float*)d_in[14];
    float* out = (float*)d_out;

    float *Q, *K, *V, *QH, *KH, *VH, *KP, *VP, *Sb, *OH, *ATT;
    cudaGetSymbolAddress((void**)&Q,  g_Q);
    cudaGetSymbolAddress((void**)&K,  g_K);
    cudaGetSymbolAddress((void**)&V,  g_V);
    cudaGetSymbolAddress((void**)&QH, g_QH);
    cudaGetSymbolAddress((void**)&KH, g_KH);
    cudaGetSymbolAddress((void**)&VH, g_VH);
    cudaGetSymbolAddress((void**)&KP, g_KP);
    cudaGetSymbolAddress((void**)&VP, g_VP);
    cudaGetSymbolAddress((void**)&Sb, g_S);
    cudaGetSymbolAddress((void**)&OH, g_OH);
    cudaGetSymbolAddress((void**)&ATT, g_ATT);

    const dim3 blk(256);
    const float alpha_s = 0.08838834764831845f;   // 1/sqrt(128)
    const int scales[4] = {1, 2, 4, 8};

    // ---- 1. input projections: Q/K/V = X @ W^T + b  (8192x1024x1024)
    dim3 g1(HID / BN, MROWS / BM, 1);
    gemm_kernel<true><<<g1, blk>>>(query, wq, bq, Q, MROWS, HID, HID, HID, HID, HID,
                                   0, 0, 0, 0, 0, 0, 1, 1.f);
    gemm_kernel<true><<<g1, blk>>>(key_,  wk, bk, K, MROWS, HID, HID, HID, HID, HID,
                                   0, 0, 0, 0, 0, 0, 1, 1.f);
    gemm_kernel<true><<<g1, blk>>>(value, wv, bv, V, MROWS, HID, HID, HID, HID, HID,
                                   0, 0, 0, 0, 0, 0, 1, 1.f);

    for (int i = 0; i < 4; i++) {
        const int s  = scales[i];
        const int Lk = SEQ / s;
        const int Mk = BATCH * Lk;
        float* QHi = QH + (long long)i * MROWS * DS;
        float* KHi = KH + (long long)i * MROWS * DS;
        float* VHi = VH + (long long)i * MROWS * DS;
        const float* wi = in_w + (long long)i * 3 * DS * DS;
        const float* bi = in_b + (long long)i * 3 * DS;

        // ---- 2. per-scale q head projection: QH = Q[:, i*DS:] @ wq_i^T + bq_i
        dim3 gq(DS / BN, MROWS / BM, 1);
        gemm_kernel<true><<<gq, blk>>>(Q + i * DS, wi, bi, QHi,
                                       MROWS, DS, DS, HID, DS, DS,
                                       0, 0, 0, 0, 0, 0, 1, 1.f);

        // ---- 3. pooled k/v sources
        const float* kSrc; const float* vSrc; int pl;
        if (s == 1) { kSrc = K + i * DS; vSrc = V + i * DS; pl = HID; }
        else {
            float* KPi = KP + (long long)i * BATCH * (SEQ / 2) * DS;
            float* VPi = VP + (long long)i * BATCH * (SEQ / 2) * DS;
            int total = Mk * DS;
            pool_kernel<<<(total + 255) / 256, 256>>>(K, KPi, Mk, s, i * DS);
            pool_kernel<<<(total + 255) / 256, 256>>>(V, VPi, Mk, s, i * DS);
            kSrc = KPi; vSrc = VPi; pl = DS;
        }

        // ---- 4. k/v head projections
        dim3 gk(DS / BN, Mk / BM, 1);
        gemm_kernel<true><<<gk, blk>>>(kSrc, wi + DS * DS, bi + DS, KHi,
                                       Mk, DS, DS, pl, DS, DS,
                                       0, 0, 0, 0, 0, 0, 1, 1.f);
        gemm_kernel<true><<<gk, blk>>>(vSrc, wi + 2 * DS * DS, bi + 2 * DS, VHi,
                                       Mk, DS, DS, pl, DS, DS,
                                       0, 0, 0, 0, 0, 0, 1, 1.f);

        // ---- 5. scores = (QH @ KH^T) / sqrt(hd)   batched over B*NH heads
        dim3 gs(Lk / BN, SEQ / BM, BATCH * NH);
        gemm_kernel<true><<<gs, blk>>>(QHi, KHi, nullptr, Sb,
                                       SEQ, Lk, HD, DS, DS, Lk,
                                       (long long)SEQ * DS, HD,
                                       (long long)Lk * DS,  HD,
                                       (long long)NH * SEQ * Lk, (long long)SEQ * Lk,
                                       NH, alpha_s);

        // ---- 6. row softmax (in place)
        dim3 gsm(SEQ, BATCH * NH);
        softmax_kernel<<<gsm, 256>>>(Sb, Lk);

        // ---- 7. weights0 = mean over heads (scale 0 only)
        if (i == 0 && (long long)out_size >= (long long)MROWS * HID + (long long)BATCH * SEQ * SEQ) {
            long long tot = (long long)BATCH * SEQ * SEQ;
            meanw_kernel<<<(unsigned)((tot + 255) / 256), 256>>>(Sb, out + (long long)MROWS * HID);
        }

        // ---- 8. OH = P @ VH  (NN, batched)
        dim3 go(HD / BN, SEQ / BM, BATCH * NH);
        gemm_kernel<false><<<go, blk>>>(Sb, VHi, nullptr, OH,
                                        SEQ, HD, Lk, Lk, DS, DS,
                                        (long long)NH * SEQ * Lk, (long long)SEQ * Lk,
                                        (long long)Lk * DS, HD,
                                        (long long)SEQ * DS, HD,
                                        NH, 1.f);

        // ---- 9. out projection into concat buffer column block i
        dim3 gp(DS / BN, MROWS / BM, 1);
        gemm_kernel<true><<<gp, blk>>>(OH, out_w + (long long)i * DS * DS, out_b + i * DS,
                                       ATT + i * DS,
                                       MROWS, DS, DS, DS, DS, HID,
                                       0, 0, 0, 0, 0, 0, 1, 1.f);
    }

    // ---- 10. fusion: out = ATT @ fus_w^T + fus_b
    gemm_kernel<true><<<g1, blk>>>(ATT, fus_w, fus_b, out, MROWS, HID, HID, HID, HID, HID,
                                   0, 0, 0, 0, 0, 0, 1, 1.f);
}

// round 3
// speedup vs baseline: 2.1299x; 2.1299x over previous
#include <cuda_runtime.h>
#include <cuda_bf16.h>
#include <math.h>
#include <stdint.h>

// ---------------- problem constants ----------------
#define BATCH   4
#define SEQ     2048
#define HID     1024
#define DS      256          // per-scale dim
#define NH      2            // heads per scale
#define HD      128          // head dim
#define MROWS   (BATCH*SEQ)  // 8192

// ---------------- scratch (device globals; no allocation allowed) ----------------
__device__ float g_Q [MROWS*HID];
__device__ float g_K [MROWS*HID];
__device__ float g_V [MROWS*HID];
__device__ float g_QH[4L*MROWS*DS];
__device__ float g_KH[4L*MROWS*DS];
__device__ float g_VH[4L*MROWS*DS];
__device__ float g_VT[MROWS*DS];                      // transposed V heads (per scale, reused)
__device__ float g_KP[4L*BATCH*(SEQ/2)*DS];
__device__ float g_VP[4L*BATCH*(SEQ/2)*DS];
__device__ float g_S [(long long)BATCH*NH*SEQ*SEQ];   // scores (reused per scale)
__device__ float g_OH[MROWS*DS];                      // reused per scale
__device__ float g_ATT[MROWS*HID];

// ---------------- helpers ----------------
__device__ __forceinline__ uint32_t smem_u32(const void* p) {
    uint32_t a;
    asm("{ .reg .u64 t; cvta.to.shared.u64 t, %1; cvt.u32.u64 %0, t; }" : "=r"(a) : "l"(p));
    return a;
}

__device__ __forceinline__ void ldm4(uint32_t* r, uint32_t addr) {
    asm volatile("ldmatrix.sync.aligned.m8n8.x4.shared.b16 {%0,%1,%2,%3}, [%4];"
                 : "=r"(r[0]), "=r"(r[1]), "=r"(r[2]), "=r"(r[3]) : "r"(addr));
}

__device__ __forceinline__ void mma_bf16(float* c, const uint32_t* a, uint32_t b0, uint32_t b1) {
    asm volatile("mma.sync.aligned.m16n8k16.row.col.f32.bf16.bf16.f32 "
                 "{%0,%1,%2,%3},{%4,%5,%6,%7},{%8,%9},{%0,%1,%2,%3};"
                 : "+f"(c[0]), "+f"(c[1]), "+f"(c[2]), "+f"(c[3])
                 : "r"(a[0]), "r"(a[1]), "r"(a[2]), "r"(a[3]), "r"(b0), "r"(b1));
}

// ---------------- bf16x2 split tensor-core GEMM ----------------
// C = alpha * A @ B^T + bias.  A: M x K row-major (lda), B: N x K row-major (ldb).
// All of M, N multiples of 128; K multiple of 32 (true for every call site).
// Batched over blockIdx.z = b*nh + h with independent strides.
#define BM 128
#define BN 128
#define BKS 32
#define LDT 40   // smem row stride in bf16 elems (80B: conflict-free for ldmatrix)

__global__ void __launch_bounds__(256)
gemm_bf16x2(const float* __restrict__ A, const float* __restrict__ Bm,
            const float* __restrict__ bias, float* __restrict__ C,
            int M, int N, int K, int lda, int ldb, int ldc,
            long long sAb, long long sAh, long long sBb, long long sBh,
            long long sCb, long long sCh, int nh, float alpha)
{
    int z = blockIdx.z;
    int bb = z / nh, hh = z - bb * nh;
    A  += (long long)bb * sAb + (long long)hh * sAh;
    Bm += (long long)bb * sBb + (long long)hh * sBh;
    C  += (long long)bb * sCb + (long long)hh * sCh;

    __shared__ __nv_bfloat16 Ahs[BM * LDT];
    __shared__ __nv_bfloat16 Als[BM * LDT];
    __shared__ __nv_bfloat16 Bhs[BN * LDT];
    __shared__ __nv_bfloat16 Bls[BN * LDT];

    const int tid   = threadIdx.x;
    const int lane  = tid & 31;
    const int wid   = tid >> 5;
    const int warpM = wid & 3;          // 4 warps in m
    const int warpN = wid >> 2;         // 2 warps in n
    const int row0  = blockIdx.y * BM;
    const int col0  = blockIdx.x * BN;

    // global tile load indices: 8 threads per row (4 floats each), 32 rows per wave
    const int gr = tid >> 3;            // 0..31
    const int gc = (tid & 7) << 2;      // 0,4,...,28

    float4 aReg[4], bReg[4];

    // ldmatrix base offsets (bytes)
    const uint32_t sAhB = smem_u32(Ahs), sAlB = smem_u32(Als);
    const uint32_t sBhB = smem_u32(Bhs), sBlB = smem_u32(Bls);
    const int aRow = warpM * 32 + (lane & 7) + ((lane >> 3) & 1) * 8;
    const int aCol = (lane >> 4) * 8;
    const int bRow = warpN * 64 + (lane & 7) + (lane >> 4) * 8;
    const int bCol = ((lane >> 3) & 1) * 8;

    uint32_t aOff[2], bOff[4];
#pragma unroll
    for (int mi = 0; mi < 2; mi++) aOff[mi] = (uint32_t)(((aRow + mi * 16) * LDT + aCol) * 2);
#pragma unroll
    for (int p = 0; p < 4; p++)    bOff[p] = (uint32_t)(((bRow + p * 16) * LDT + bCol) * 2);

    float acc[2][8][4];
#pragma unroll
    for (int mi = 0; mi < 2; mi++)
#pragma unroll
        for (int na = 0; na < 8; na++)
#pragma unroll
            for (int q = 0; q < 4; q++) acc[mi][na][q] = 0.f;

    auto ldTiles = [&](int k0) {
#pragma unroll
        for (int it = 0; it < 4; ++it) {
            aReg[it] = *(const float4*)(A  + (long long)(row0 + gr + it * 32) * lda + k0 + gc);
            bReg[it] = *(const float4*)(Bm + (long long)(col0 + gr + it * 32) * ldb + k0 + gc);
        }
    };
    auto stTiles = [&]() {
#pragma unroll
        for (int it = 0; it < 4; ++it) {
            float va[4] = {aReg[it].x, aReg[it].y, aReg[it].z, aReg[it].w};
            float vb[4] = {bReg[it].x, bReg[it].y, bReg[it].z, bReg[it].w};
            union Pk { __nv_bfloat16 b[4]; uint2 u; } ah, al, bh, bl;
#pragma unroll
            for (int j = 0; j < 4; j++) {
                __nv_bfloat16 h = __float2bfloat16(va[j]);
                ah.b[j] = h;
                al.b[j] = __float2bfloat16(va[j] - __bfloat162float(h));
                __nv_bfloat16 h2 = __float2bfloat16(vb[j]);
                bh.b[j] = h2;
                bl.b[j] = __float2bfloat16(vb[j] - __bfloat162float(h2));
            }
            int off = (gr + it * 32) * LDT + gc;
            *(uint2*)&Ahs[off] = ah.u;
            *(uint2*)&Als[off] = al.u;
            *(uint2*)&Bhs[off] = bh.u;
            *(uint2*)&Bls[off] = bl.u;
        }
    };

    ldTiles(0);
    stTiles();
    __syncthreads();

    for (int k0 = 0; k0 < K; k0 += BKS) {
        const bool more = (k0 + BKS) < K;
        if (more) ldTiles(k0 + BKS);

#pragma unroll
        for (int ka = 0; ka < BKS; ka += 16) {
            uint32_t ah[2][4], al[2][4];
#pragma unroll
            for (int mi = 0; mi < 2; mi++) {
                ldm4(ah[mi], sAhB + aOff[mi] + ka * 2);
                ldm4(al[mi], sAlB + aOff[mi] + ka * 2);
            }
#pragma unroll
            for (int p = 0; p < 4; p++) {
                uint32_t bh[4], bl[4];
                ldm4(bh, sBhB + bOff[p] + ka * 2);
                ldm4(bl, sBlB + bOff[p] + ka * 2);
#pragma unroll
                for (int mi = 0; mi < 2; mi++) {
#pragma unroll
                    for (int s = 0; s < 2; s++) {
                        int na = p * 2 + s;
                        mma_bf16(acc[mi][na], ah[mi], bh[2 * s], bh[2 * s + 1]);
                        mma_bf16(acc[mi][na], ah[mi], bl[2 * s], bl[2 * s + 1]);
                        mma_bf16(acc[mi][na], al[mi], bh[2 * s], bh[2 * s + 1]);
                    }
                }
            }
        }
        __syncthreads();
        if (more) { stTiles(); __syncthreads(); }
    }

    // epilogue: c0,c1 -> (r, c), (r, c+1); c2,c3 -> (r+8, c), (r+8, c+1)
    const int crow  = row0 + warpM * 32 + (lane >> 2);
    const int ccol0 = col0 + warpN * 64 + (lane & 3) * 2;
#pragma unroll
    for (int mi = 0; mi < 2; mi++) {
#pragma unroll
        for (int na = 0; na < 8; na++) {
            int r = crow + mi * 16;
            int c = ccol0 + na * 8;
            float b0 = bias ? bias[c]     : 0.f;
            float b1 = bias ? bias[c + 1] : 0.f;
            float2 v0 = make_float2(acc[mi][na][0] * alpha + b0, acc[mi][na][1] * alpha + b1);
            float2 v1 = make_float2(acc[mi][na][2] * alpha + b0, acc[mi][na][3] * alpha + b1);
            *(float2*)&C[(long long)r * ldc + c]       = v0;
            *(float2*)&C[(long long)(r + 8) * ldc + c] = v1;
        }
    }
}

// ---------------- avg-pool of a DS-wide column slice along seq ----------------
__global__ void pool_kernel(const float* __restrict__ X, float* __restrict__ Y,
                            int rows, int s, int colOff)
{
    int idx = blockIdx.x * blockDim.x + threadIdx.x;
    int total = rows * DS;
    if (idx >= total) return;
    int r = idx / DS, c = idx - r * DS;
    const float* src = X + (long long)r * s * HID + colOff + c;
    float acc = 0.f;
    for (int j = 0; j < s; j++) acc += src[(long long)j * HID];
    Y[idx] = acc * (1.f / s);
}

// ---------------- transpose V heads: X [B][Lk][DS] -> Y [B][NH][HD][Lk] ----------------
__global__ void transpose_vh(const float* __restrict__ X, float* __restrict__ Y, int Lk)
{
    __shared__ float t[32][33];
    int b  = blockIdx.z;
    int k0 = blockIdx.x * 32, d0 = blockIdx.y * 32;
    int tx = threadIdx.x, ty = threadIdx.y;   // 32 x 8
#pragma unroll
    for (int j = 0; j < 32; j += 8)
        t[ty + j][tx] = X[((long long)b * Lk + k0 + ty + j) * DS + d0 + tx];
    __syncthreads();
    int head = d0 >> 7;
    int dh0  = d0 & 127;
#pragma unroll
    for (int j = 0; j < 32; j += 8) {
        int d = dh0 + ty + j;
        Y[(long long)b * DS * Lk + (long long)head * HD * Lk + (long long)d * Lk + k0 + tx]
            = t[tx][ty + j];
    }
}

// ---------------- in-place row softmax ----------------
__global__ void softmax_kernel(float* __restrict__ S, int Lk)
{
    long long row = (long long)blockIdx.y * gridDim.x + blockIdx.x;
    float* p = S + row * Lk;
    __shared__ float red[256];
    int tid = threadIdx.x;

    float m = -1e30f;
    for (int i = tid; i < Lk; i += 256) m = fmaxf(m, p[i]);
    red[tid] = m; __syncthreads();
    for (int s = 128; s > 0; s >>= 1) {
        if (tid < s) red[tid] = fmaxf(red[tid], red[tid + s]);
        __syncthreads();
    }
    m = red[0]; __syncthreads();

    float sum = 0.f;
    for (int i = tid; i < Lk; i += 256) {
        float e = __expf(p[i] - m);
        p[i] = e; sum += e;
    }
    red[tid] = sum; __syncthreads();
    for (int s = 128; s > 0; s >>= 1) {
        if (tid < s) red[tid] += red[tid + s];
        __syncthreads();
    }
    float inv = 1.f / red[0];
    for (int i = tid; i < Lk; i += 256) p[i] *= inv;
}

// ---------------- mean of 2 heads of scale-0 probs -> weights0 ----------------
__global__ void meanw_kernel(const float* __restrict__ S, float* __restrict__ W)
{
    long long idx = (long long)blockIdx.x * blockDim.x + threadIdx.x;
    const long long per = (long long)SEQ * SEQ;
    const long long total = (long long)BATCH * per;
    if (idx >= total) return;
    long long b = idx / per, rest = idx - b * per;
    W[idx] = 0.5f * (S[(b * 2 + 0) * per + rest] + S[(b * 2 + 1) * per + rest]);
}

// ---------------- host orchestration ----------------
extern "C" void kernel_launch(void* const* d_in, const int* in_sizes, int n_in,
                              void* d_out, int out_size)
{
    const float* query = (const float*)d_in[0];
    const float* key_  = (const float*)d_in[1];
    const float* value = (const float*)d_in[2];
    const float* wq    = (const float*)d_in[3];
    const float* bq    = (const float*)d_in[4];
    const float* wk    = (const float*)d_in[5];
    const float* bk    = (const float*)d_in[6];
    const float* wv    = (const float*)d_in[7];
    const float* bv    = (const float*)d_in[8];
    const float* in_w  = (const float*)d_in[9];   // (4, 768, 256)
    const float* in_b  = (const float*)d_in[10];  // (4, 768)
    const float* out_w = (const float*)d_in[11];  // (4, 256, 256)
    const float* out_b = (const float*)d_in[12];  // (4, 256)
    const float* fus_w = (const float*)d_in[13];
    const float* fus_b = (const float*)d_in[14];
    float* out = (float*)d_out;

    float *Q, *K, *V, *QH, *KH, *VH, *VT, *KP, *VP, *Sb, *OH, *ATT;
    cudaGetSymbolAddress((void**)&Q,  g_Q);
    cudaGetSymbolAddress((void**)&K,  g_K);
    cudaGetSymbolAddress((void**)&V,  g_V);
    cudaGetSymbolAddress((void**)&QH, g_QH);
    cudaGetSymbolAddress((void**)&KH, g_KH);
    cudaGetSymbolAddress((void**)&VH, g_VH);
    cudaGetSymbolAddress((void**)&VT, g_VT);
    cudaGetSymbolAddress((void**)&KP, g_KP);
    cudaGetSymbolAddress((void**)&VP, g_VP);
    cudaGetSymbolAddress((void**)&Sb, g_S);
    cudaGetSymbolAddress((void**)&OH, g_OH);
    cudaGetSymbolAddress((void**)&ATT, g_ATT);

    const dim3 blk(256);
    const float alpha_s = 0.08838834764831845f;   // 1/sqrt(128)
    const int scales[4] = {1, 2, 4, 8};

    // ---- 1. input projections: Q/K/V = X @ W^T + b
    dim3 g1(HID / BN, MROWS / BM, 1);
    gemm_bf16x2<<<g1, blk>>>(query, wq, bq, Q, MROWS, HID, HID, HID, HID, HID,
                             0, 0, 0, 0, 0, 0, 1, 1.f);
    gemm_bf16x2<<<g1, blk>>>(key_,  wk, bk, K, MROWS, HID, HID, HID, HID, HID,
                             0, 0, 0, 0, 0, 0, 1, 1.f);
    gemm_bf16x2<<<g1, blk>>>(value, wv, bv, V, MROWS, HID, HID, HID, HID, HID,
                             0, 0, 0, 0, 0, 0, 1, 1.f);

    for (int i = 0; i < 4; i++) {
        const int s  = scales[i];
        const int Lk = SEQ / s;
        const int Mk = BATCH * Lk;
        float* QHi = QH + (long long)i * MROWS * DS;
        float* KHi = KH + (long long)i * MROWS * DS;
        float* VHi = VH + (long long)i * MROWS * DS;
        const float* wi = in_w + (long long)i * 3 * DS * DS;
        const float* bi = in_b + (long long)i * 3 * DS;

        // ---- 2. q head projection
        dim3 gq(DS / BN, MROWS / BM, 1);
        gemm_bf16x2<<<gq, blk>>>(Q + i * DS, wi, bi, QHi,
                                 MROWS, DS, DS, HID, DS, DS,
                                 0, 0, 0, 0, 0, 0, 1, 1.f);

        // ---- 3. pooled k/v sources
        const float* kSrc; const float* vSrc; int pl;
        if (s == 1) { kSrc = K + i * DS; vSrc = V + i * DS; pl = HID; }
        else {
            float* KPi = KP + (long long)i * BATCH * (SEQ / 2) * DS;
            float* VPi = VP + (long long)i * BATCH * (SEQ / 2) * DS;
            int total = Mk * DS;
            pool_kernel<<<(total + 255) / 256, 256>>>(K, KPi, Mk, s, i * DS);
            pool_kernel<<<(total + 255) / 256, 256>>>(V, VPi, Mk, s, i * DS);
            kSrc = KPi; vSrc = VPi; pl = DS;
        }

        // ---- 4. k/v head projections
        dim3 gk(DS / BN, Mk / BM, 1);
        gemm_bf16x2<<<gk, blk>>>(kSrc, wi + DS * DS, bi + DS, KHi,
                                 Mk, DS, DS, pl, DS, DS,
                                 0, 0, 0, 0, 0, 0, 1, 1.f);
        gemm_bf16x2<<<gk, blk>>>(vSrc, wi + 2 * DS * DS, bi + 2 * DS, VHi,
                                 Mk, DS, DS, pl, DS, DS,
                                 0, 0, 0, 0, 0, 0, 1, 1.f);

        // ---- 4b. transpose V heads: VT[b][h][d][k]
        {
            dim3 gt(Lk / 32, DS / 32, BATCH);
            transpose_vh<<<gt, dim3(32, 8)>>>(VHi, VT, Lk);
        }

        // ---- 5. scores = (QH @ KH^T) / sqrt(hd)   batched over B*NH heads
        dim3 gs(Lk / BN, SEQ / BM, BATCH * NH);
        gemm_bf16x2<<<gs, blk>>>(QHi, KHi, nullptr, Sb,
                                 SEQ, Lk, HD, DS, DS, Lk,
                                 (long long)SEQ * DS, HD,
                                 (long long)Lk * DS,  HD,
                                 (long long)NH * SEQ * Lk, (long long)SEQ * Lk,
                                 NH, alpha_s);

        // ---- 6. row softmax (in place)
        dim3 gsm(SEQ, BATCH * NH);
        softmax_kernel<<<gsm, 256>>>(Sb, Lk);

        // ---- 7. weights0 = mean over heads (scale 0 only)
        if (i == 0 && (long long)out_size >= (long long)MROWS * HID + (long long)BATCH * SEQ * SEQ) {
            long long tot = (long long)BATCH * SEQ * SEQ;
            meanw_kernel<<<(unsigned)((tot + 255) / 256), 256>>>(Sb, out + (long long)MROWS * HID);
        }

        // ---- 8. OH = P @ VH  (via transposed V: TB GEMM, N=HD)
        dim3 go(HD / BN, SEQ / BM, BATCH * NH);
        gemm_bf16x2<<<go, blk>>>(Sb, VT, nullptr, OH,
                                 SEQ, HD, Lk, Lk, Lk, DS,
                                 (long long)NH * SEQ * Lk, (long long)SEQ * Lk,
                                 (long long)DS * Lk, (long long)HD * Lk,
                                 (long long)SEQ * DS, HD,
                                 NH, 1.f);

        // ---- 9. out projection into concat buffer column block i
        dim3 gp(DS / BN, MROWS / BM, 1);
        gemm_bf16x2<<<gp, blk>>>(OH, out_w + (long long)i * DS * DS, out_b + i * DS,
                                 ATT + i * DS,
                                 MROWS, DS, DS, DS, DS, HID,
                                 0, 0, 0, 0, 0, 0, 1, 1.f);
    }

    // ---- 10. fusion: out = ATT @ fus_w^T + fus_b
    gemm_bf16x2<<<g1, blk>>>(ATT, fus_w, fus_b, out, MROWS, HID, HID, HID, HID, HID,
                             0, 0, 0, 0, 0, 0, 1, 1.f);
}